// round 3
// baseline (speedup 1.0000x reference)
#include <cuda_runtime.h>

#define SQ 2048
#define HID 1024
#define HEADS 16
#define HD 64
#define BSZ 2
#define BH (BSZ*HEADS)
#define ROWS_TOT (BSZ*SQ)

// scratch (allocation-free: device globals)
__device__ float g_q[BH*SQ*HD];
__device__ float g_k[BH*SQ*HD];
__device__ float g_v[BH*SQ*HD];
__device__ float g_vp[BH*SQ*HD];
__device__ float g_att[ROWS_TOT*HID];
__device__ float g_mod[HID];
__device__ float g_cs[SQ];
__device__ float g_sn[SQ];

__device__ __forceinline__ float tf32r(float x) {
    float y;
    asm("cvt.rna.tf32.f32 %0, %1;" : "=f"(y) : "f"(x));
    return y;
}
__device__ __forceinline__ unsigned fu(float x) { return __float_as_uint(x); }

#define MMA_TF32(d, a0, a1, a2, a3, b0, b1)                                        \
    asm volatile(                                                                   \
        "mma.sync.aligned.m16n8k8.row.col.f32.tf32.tf32.f32 "                       \
        "{%0,%1,%2,%3},{%4,%5,%6,%7},{%8,%9},{%0,%1,%2,%3};"                        \
        : "+f"(d[0]), "+f"(d[1]), "+f"(d[2]), "+f"(d[3])                            \
        : "r"(a0), "r"(a1), "r"(a2), "r"(a3), "r"(b0), "r"(b1))

// ---------------------------------------------------------------- prep
__global__ void prep_kernel(const float* __restrict__ phase,
                            const float* __restrict__ amp) {
    int i = blockIdx.x * 256 + threadIdx.x;
    if (i < HID) g_mod[i] = cosf(phase[i]) * amp[i];
    if (i < SQ) {
        float a = 6.283185307179586f * (float)i / (float)SQ;
        g_cs[i] = cosf(a);
        g_sn[i] = sinf(a);
    }
}

// ---------------------------------------------------------------- V roll
__global__ void roll_kernel() {
    int idx = blockIdx.x * 256 + threadIdx.x;  // float4 index
    if (idx >= BH * SQ * (HD / 4)) return;
    int d4 = idx & 15;
    int rest = idx >> 4;
    int s = rest & (SQ - 1);
    int bh = rest >> 11;
    int s2 = (s + 1) & (SQ - 1);
    const float4* v = (const float4*)g_v;
    float4 a = v[(((size_t)bh * SQ + s) << 4) + d4];
    float4 b = v[(((size_t)bh * SQ + s2) << 4) + d4];
    float4 o;
    const float r = 0.7071067811865476f;
    o.x = (a.x + b.x) * r;
    o.y = (a.y + b.y) * r;
    o.z = (a.z + b.z) * r;
    o.w = (a.w + b.w) * r;
    ((float4*)g_vp)[idx] = o;
}

// ---------------------------------------------------------------- TF32 GEMM (QKV)
// C = X[4096,1024] @ W[1024,1024], tile 128x128, kblock 32, 8 warps 2m x 4n.
// A stored in paired-k layout: within each 8-k group, order [k0,k4,k1,k5,k2,k6,k3,k7]
#define LDA 40
#define LDB 136
#define GEMM_SMEM ((2*128*LDA + 2*32*LDB) * 4)

__device__ __forceinline__ void store_a_paired(float* dst, const float4* pa) {
    float4 y0 = {tf32r(pa[0].x), tf32r(pa[1].x), tf32r(pa[0].y), tf32r(pa[1].y)};
    float4 y1 = {tf32r(pa[0].z), tf32r(pa[1].z), tf32r(pa[0].w), tf32r(pa[1].w)};
    float4 y2 = {tf32r(pa[2].x), tf32r(pa[3].x), tf32r(pa[2].y), tf32r(pa[3].y)};
    float4 y3 = {tf32r(pa[2].z), tf32r(pa[3].z), tf32r(pa[2].w), tf32r(pa[3].w)};
    *(float4*)(dst + 0) = y0;
    *(float4*)(dst + 4) = y1;
    *(float4*)(dst + 8) = y2;
    *(float4*)(dst + 12) = y3;
}

__global__ __launch_bounds__(256, 2) void qkv_gemm(const float* __restrict__ X,
                                                   const float* __restrict__ Wq,
                                                   const float* __restrict__ Wk,
                                                   const float* __restrict__ Wv) {
    extern __shared__ float smg[];
    float* As = smg;                  // [2][128*LDA] paired-k
    float* Bs = smg + 2 * 128 * LDA;  // [2][32*LDB]

    int mode = blockIdx.z;
    const float* W = (mode == 0) ? Wq : (mode == 1) ? Wk : Wv;
    float* dst = (mode == 0) ? g_q : (mode == 1) ? g_k : g_v;

    int bn = blockIdx.x, bm = blockIdx.y;
    int tid = threadIdx.x, lane = tid & 31, w = tid >> 5;
    int wm = w >> 2, wn = w & 3;
    int r = lane >> 2, c = lane & 3;

    int arow = tid >> 1, acol0 = (tid & 1) * 16;
    int brow = tid >> 3, bcol0 = (tid & 7) * 16;
    const float* Ag = X + (size_t)(bm * 128 + arow) * HID + acol0;
    const float* Bg = W + (size_t)brow * HID + bn * 128 + bcol0;

    float4 pa[4], pb[4];
#pragma unroll
    for (int q = 0; q < 4; q++) {
        pa[q] = *(const float4*)(Ag + q * 4);
        pb[q] = *(const float4*)(Bg + q * 4);
    }
    store_a_paired(&As[arow * LDA + acol0], pa);
#pragma unroll
    for (int q = 0; q < 4; q++) {
        float4 tb = {tf32r(pb[q].x), tf32r(pb[q].y), tf32r(pb[q].z), tf32r(pb[q].w)};
        *(float4*)&Bs[brow * LDB + bcol0 + q * 4] = tb;
    }
    __syncthreads();

    float acc[4][4][4];
#pragma unroll
    for (int i = 0; i < 4; i++)
#pragma unroll
        for (int j = 0; j < 4; j++)
#pragma unroll
            for (int e = 0; e < 4; e++) acc[i][j][e] = 0.f;

    for (int kb = 0; kb < 32; kb++) {
        const float* Ac = As + (kb & 1) * (128 * LDA);
        const float* Bc = Bs + (kb & 1) * (32 * LDB);
        if (kb < 31) {
            const float* Ag2 = Ag + (kb + 1) * 32;
            const float* Bg2 = Bg + (size_t)(kb + 1) * 32 * HID;
#pragma unroll
            for (int q = 0; q < 4; q++) {
                pa[q] = *(const float4*)(Ag2 + q * 4);
                pb[q] = *(const float4*)(Bg2 + q * 4);
            }
        }
#pragma unroll
        for (int kk = 0; kk < 4; kk++) {
            unsigned a[4][4], b[4][2];
#pragma unroll
            for (int i = 0; i < 4; i++) {
                const float* p = Ac + (wm * 64 + i * 16 + r) * LDA + kk * 8 + 2 * c;
                float2 lo = *(const float2*)p;
                float2 hi = *(const float2*)(p + 8 * LDA);
                a[i][0] = fu(lo.x);
                a[i][1] = fu(hi.x);
                a[i][2] = fu(lo.y);
                a[i][3] = fu(hi.y);
            }
#pragma unroll
            for (int j = 0; j < 4; j++) {
                const float* p = Bc + (kk * 8 + c) * LDB + wn * 32 + j * 8 + r;
                b[j][0] = fu(p[0]);
                b[j][1] = fu(p[4 * LDB]);
            }
#pragma unroll
            for (int i = 0; i < 4; i++)
#pragma unroll
                for (int j = 0; j < 4; j++)
                    MMA_TF32(acc[i][j], a[i][0], a[i][1], a[i][2], a[i][3],
                             b[j][0], b[j][1]);
        }
        if (kb < 31) {
            float* An = As + ((kb + 1) & 1) * (128 * LDA);
            float* Bn = Bs + ((kb + 1) & 1) * (32 * LDB);
            store_a_paired(&An[arow * LDA + acol0], pa);
#pragma unroll
            for (int q = 0; q < 4; q++) {
                float4 tb = {tf32r(pb[q].x), tf32r(pb[q].y), tf32r(pb[q].z), tf32r(pb[q].w)};
                *(float4*)&Bn[brow * LDB + bcol0 + q * 4] = tb;
            }
            __syncthreads();
        }
    }

    // epilogue: mod scale (q also 1/8), scatter to [B,H,S,D]
    float sc = (mode == 0) ? 0.125f : 1.0f;
#pragma unroll
    for (int i = 0; i < 4; i++) {
#pragma unroll
        for (int ro = 0; ro < 2; ro++) {
            int grow = bm * 128 + wm * 64 + i * 16 + r + ro * 8;
            int bb = grow >> 11;
            int ss = grow & 2047;
#pragma unroll
            for (int j = 0; j < 4; j++) {
                int col = bn * 128 + wn * 32 + j * 8 + 2 * c;
                int hh = col >> 6;
                int dd = col & 63;
                float m0v = g_mod[col] * sc;
                float m1v = g_mod[col + 1] * sc;
                float2 v;
                v.x = acc[i][j][ro * 2 + 0] * m0v;
                v.y = acc[i][j][ro * 2 + 1] * m1v;
                *(float2*)&dst[(((size_t)(bb * HEADS + hh) * SQ + ss) * HD + dd)] = v;
            }
        }
    }
}

// ---------------------------------------------------------------- TF32 GEMM (out)
__global__ __launch_bounds__(256, 2) void out_gemm(const float* __restrict__ W,
                                                   float* __restrict__ C) {
    extern __shared__ float smg[];
    float* As = smg;
    float* Bs = smg + 2 * 128 * LDA;

    int bn = blockIdx.x, bm = blockIdx.y;
    int tid = threadIdx.x, lane = tid & 31, w = tid >> 5;
    int wm = w >> 2, wn = w & 3;
    int r = lane >> 2, c = lane & 3;

    int arow = tid >> 1, acol0 = (tid & 1) * 16;
    int brow = tid >> 3, bcol0 = (tid & 7) * 16;
    const float* Ag = g_att + (size_t)(bm * 128 + arow) * HID + acol0;
    const float* Bg = W + (size_t)brow * HID + bn * 128 + bcol0;

    float4 pa[4], pb[4];
#pragma unroll
    for (int q = 0; q < 4; q++) {
        pa[q] = *(const float4*)(Ag + q * 4);
        pb[q] = *(const float4*)(Bg + q * 4);
    }
    store_a_paired(&As[arow * LDA + acol0], pa);
#pragma unroll
    for (int q = 0; q < 4; q++) {
        float4 tb = {tf32r(pb[q].x), tf32r(pb[q].y), tf32r(pb[q].z), tf32r(pb[q].w)};
        *(float4*)&Bs[brow * LDB + bcol0 + q * 4] = tb;
    }
    __syncthreads();

    float acc[4][4][4];
#pragma unroll
    for (int i = 0; i < 4; i++)
#pragma unroll
        for (int j = 0; j < 4; j++)
#pragma unroll
            for (int e = 0; e < 4; e++) acc[i][j][e] = 0.f;

    for (int kb = 0; kb < 32; kb++) {
        const float* Ac = As + (kb & 1) * (128 * LDA);
        const float* Bc = Bs + (kb & 1) * (32 * LDB);
        if (kb < 31) {
            const float* Ag2 = Ag + (kb + 1) * 32;
            const float* Bg2 = Bg + (size_t)(kb + 1) * 32 * HID;
#pragma unroll
            for (int q = 0; q < 4; q++) {
                pa[q] = *(const float4*)(Ag2 + q * 4);
                pb[q] = *(const float4*)(Bg2 + q * 4);
            }
        }
#pragma unroll
        for (int kk = 0; kk < 4; kk++) {
            unsigned a[4][4], b[4][2];
#pragma unroll
            for (int i = 0; i < 4; i++) {
                const float* p = Ac + (wm * 64 + i * 16 + r) * LDA + kk * 8 + 2 * c;
                float2 lo = *(const float2*)p;
                float2 hi = *(const float2*)(p + 8 * LDA);
                a[i][0] = fu(lo.x);
                a[i][1] = fu(hi.x);
                a[i][2] = fu(lo.y);
                a[i][3] = fu(hi.y);
            }
#pragma unroll
            for (int j = 0; j < 4; j++) {
                const float* p = Bc + (kk * 8 + c) * LDB + wn * 32 + j * 8 + r;
                b[j][0] = fu(p[0]);
                b[j][1] = fu(p[4 * LDB]);
            }
#pragma unroll
            for (int i = 0; i < 4; i++)
#pragma unroll
                for (int j = 0; j < 4; j++)
                    MMA_TF32(acc[i][j], a[i][0], a[i][1], a[i][2], a[i][3],
                             b[j][0], b[j][1]);
        }
        if (kb < 31) {
            float* An = As + ((kb + 1) & 1) * (128 * LDA);
            float* Bn = Bs + ((kb + 1) & 1) * (32 * LDB);
            store_a_paired(&An[arow * LDA + acol0], pa);
#pragma unroll
            for (int q = 0; q < 4; q++) {
                float4 tb = {tf32r(pb[q].x), tf32r(pb[q].y), tf32r(pb[q].z), tf32r(pb[q].w)};
                *(float4*)&Bn[brow * LDB + bcol0 + q * 4] = tb;
            }
            __syncthreads();
        }
    }

#pragma unroll
    for (int i = 0; i < 4; i++) {
#pragma unroll
        for (int ro = 0; ro < 2; ro++) {
            int grow = bm * 128 + wm * 64 + i * 16 + r + ro * 8;
#pragma unroll
            for (int j = 0; j < 4; j++) {
                int col = bn * 128 + wn * 32 + j * 8 + 2 * c;
                float2 v;
                v.x = acc[i][j][ro * 2 + 0];
                v.y = acc[i][j][ro * 2 + 1];
                *(float2*)&C[(size_t)grow * HID + col] = v;
            }
        }
    }
}

// ---------------------------------------------------------------- flash attention (TF32 mma, v3)
// grid (16,16,2), 256 thr = 8 warps; warp w owns rows [w*16, w*16+16).
// M-tile 128, N-tile 64 per iteration. 2 CTAs/SM.
// Paired-k layouts for Q, K, P; V stored transposed [d][n-paired].
#define LDQ 72
#define LDK 72
#define LDVT 72
#define LDP 72
#define NT 64
#define ATT_SMEM ((128*LDQ + NT*LDK + NT*LDVT + 128*LDP + 2*NT) * 4)

__global__ __launch_bounds__(256, 2) void attn_kernel() {
    extern __shared__ float sma[];
    float* Qs = sma;                  // [128][LDQ] paired-k
    float* Ks = Qs + 128 * LDQ;       // [64][LDK] paired-k
    float* Vt = Ks + NT * LDK;        // [64 d][LDVT] n-paired
    float* Ps = Vt + NT * LDVT;       // [128][LDP] paired-k (warp-private rows)
    float* cjs = Ps + 128 * LDP;      // [64]
    float* sjs = cjs + NT;            // [64]

    int m0 = blockIdx.x * 128;
    int h = blockIdx.y, b = blockIdx.z;
    int bh = b * HEADS + h;
    const float* Qg = g_q + (size_t)bh * SQ * HD;
    const float* Kg = g_k + (size_t)bh * SQ * HD;
    const float* Vg = g_vp + (size_t)bh * SQ * HD;

    int tid = threadIdx.x, lane = tid & 31, w = tid >> 5;
    int r = lane >> 2, c = lane & 3;

    // load Q tile once (paired-k): row = tid>>1, d-half = (tid&1)*32
    {
        int row = tid >> 1;
        int dh = (tid & 1) * 32;
        const float* src = Qg + (size_t)(m0 + row) * HD + dh;
        float* drow = Qs + row * LDQ + dh;
#pragma unroll
        for (int cc = 0; cc < 4; cc++) {
            float4 x0 = *(const float4*)(src + cc * 8);
            float4 x1 = *(const float4*)(src + cc * 8 + 4);
            float4 y0 = {tf32r(x0.x), tf32r(x1.x), tf32r(x0.y), tf32r(x1.y)};
            float4 y1 = {tf32r(x0.z), tf32r(x1.z), tf32r(x0.w), tf32r(x1.w)};
            *(float4*)(drow + cc * 8) = y0;
            *(float4*)(drow + cc * 8 + 4) = y1;
        }
    }

    // per-thread row trig + online-softmax state
    float cmv[2], smv[2], ms[2], ls[2];
#pragma unroll
    for (int ro = 0; ro < 2; ro++) {
        int row = m0 + w * 16 + r + ro * 8;
        cmv[ro] = g_cs[row];
        smv[ro] = g_sn[row];
        ms[ro] = -1e30f;
        ls[ro] = 0.f;
    }
    float o[8][4];
#pragma unroll
    for (int j = 0; j < 8; j++)
#pragma unroll
        for (int e = 0; e < 4; e++) o[j][e] = 0.f;

    for (int n0 = 0; n0 < SQ; n0 += NT) {
        __syncthreads();  // previous iter's reads of Ks/Vt done (also Q store on iter 0)

        // K tile (paired-k): row = tid>>2, 2 chunk-sets
        {
            int krow = tid >> 2;
            int kcb = (tid & 3) * 8;
            const float* src = Kg + (size_t)(n0 + krow) * HD;
            float* drow = Ks + krow * LDK;
#pragma unroll
            for (int hh = 0; hh < 2; hh++) {
                int db = kcb + hh * 32;
                float4 x0 = *(const float4*)(src + db);
                float4 x1 = *(const float4*)(src + db + 4);
                float4 y0 = {tf32r(x0.x), tf32r(x1.x), tf32r(x0.y), tf32r(x1.y)};
                float4 y1 = {tf32r(x0.z), tf32r(x1.z), tf32r(x0.w), tf32r(x1.w)};
                *(float4*)(drow + db) = y0;
                *(float4*)(drow + db + 4) = y1;
            }
        }
        // V tile transposed + n-paired: d = tid&63, n-groups (tid>>6), (tid>>6)+4
        {
            int d = tid & 63;
            int ng0 = tid >> 6;
            const float* src = Vg + (size_t)n0 * HD + d;
#pragma unroll
            for (int gg = 0; gg < 2; gg++) {
                int ng = ng0 + gg * 4;
                const float* s8 = src + (size_t)(ng * 8) * HD;
                float v0 = s8[0 * HD], v4 = s8[4 * HD];
                float v1 = s8[1 * HD], v5 = s8[5 * HD];
                float v2 = s8[2 * HD], v6 = s8[6 * HD];
                float v3 = s8[3 * HD], v7 = s8[7 * HD];
                float4 y0 = {tf32r(v0), tf32r(v4), tf32r(v1), tf32r(v5)};
                float4 y1 = {tf32r(v2), tf32r(v6), tf32r(v3), tf32r(v7)};
                *(float4*)(Vt + d * LDVT + ng * 8) = y0;
                *(float4*)(Vt + d * LDVT + ng * 8 + 4) = y1;
            }
        }
        if (tid < NT) {
            cjs[tid] = g_cs[n0 + tid];
            sjs[tid] = g_sn[n0 + tid];
        }
        __syncthreads();

        // S = Q K^T : warp tile m16 x n64
        float s[8][4];
#pragma unroll
        for (int j = 0; j < 8; j++)
#pragma unroll
            for (int e = 0; e < 4; e++) s[j][e] = 0.f;

#pragma unroll
        for (int kk = 0; kk < 8; kk++) {
            float2 qlo = *(const float2*)&Qs[(w * 16 + r) * LDQ + kk * 8 + 2 * c];
            float2 qhi = *(const float2*)&Qs[(w * 16 + r + 8) * LDQ + kk * 8 + 2 * c];
            unsigned a0 = fu(qlo.x), a1 = fu(qhi.x), a2 = fu(qlo.y), a3 = fu(qhi.y);
#pragma unroll
            for (int j = 0; j < 8; j++) {
                float2 kb = *(const float2*)&Ks[(j * 8 + r) * LDK + kk * 8 + 2 * c];
                MMA_TF32(s[j], a0, a1, a2, a3, fu(kb.x), fu(kb.y));
            }
        }

        // interference modulation
#pragma unroll
        for (int j = 0; j < 8; j++) {
            float2 cjp = *(const float2*)&cjs[j * 8 + 2 * c];
            float2 sjp = *(const float2*)&sjs[j * 8 + 2 * c];
            s[j][0] *= (cmv[0] * cjp.x + smv[0] * sjp.x);
            s[j][1] *= (cmv[0] * cjp.y + smv[0] * sjp.y);
            s[j][2] *= (cmv[1] * cjp.x + smv[1] * sjp.x);
            s[j][3] *= (cmv[1] * cjp.y + smv[1] * sjp.y);
        }

        // online softmax per row group
#pragma unroll
        for (int ro = 0; ro < 2; ro++) {
            float mx = -1e30f;
#pragma unroll
            for (int j = 0; j < 8; j++)
                mx = fmaxf(mx, fmaxf(s[j][ro * 2], s[j][ro * 2 + 1]));
            mx = fmaxf(mx, __shfl_xor_sync(0xffffffffu, mx, 1));
            mx = fmaxf(mx, __shfl_xor_sync(0xffffffffu, mx, 2));
            float mn = fmaxf(ms[ro], mx);
            float al = __expf(ms[ro] - mn);
            float sum = 0.f;
#pragma unroll
            for (int j = 0; j < 8; j++) {
                float p0 = __expf(s[j][ro * 2] - mn);
                float p1 = __expf(s[j][ro * 2 + 1] - mn);
                s[j][ro * 2] = p0;
                s[j][ro * 2 + 1] = p1;
                sum += p0 + p1;
            }
            sum += __shfl_xor_sync(0xffffffffu, sum, 1);
            sum += __shfl_xor_sync(0xffffffffu, sum, 2);
            ls[ro] = ls[ro] * al + sum;
            ms[ro] = mn;
#pragma unroll
            for (int j2 = 0; j2 < 8; j2++) {
                o[j2][ro * 2] *= al;
                o[j2][ro * 2 + 1] *= al;
            }
        }

        // write P (warp-private rows, paired-k positions)
        {
            int p0 = (c < 2) ? 4 * c : 4 * c - 7;
            int p1 = (c < 2) ? 4 * c + 2 : 4 * c - 5;
            float* pr = Ps + (w * 16 + r) * LDP;
#pragma unroll
            for (int j = 0; j < 8; j++) {
                float* pj = pr + j * 8;
                pj[p0] = tf32r(s[j][0]);
                pj[p1] = tf32r(s[j][1]);
                pj[8 * LDP + p0] = tf32r(s[j][2]);
                pj[8 * LDP + p1] = tf32r(s[j][3]);
            }
        }
        __syncwarp();

        // O += P @ V' : warp tile m16 x n64, k = NT
#pragma unroll
        for (int kk = 0; kk < 8; kk++) {
            float2 plo = *(const float2*)&Ps[(w * 16 + r) * LDP + kk * 8 + 2 * c];
            float2 phi = *(const float2*)&Ps[(w * 16 + r + 8) * LDP + kk * 8 + 2 * c];
            unsigned a0 = fu(plo.x), a1 = fu(phi.x), a2 = fu(plo.y), a3 = fu(phi.y);
#pragma unroll
            for (int j2 = 0; j2 < 8; j2++) {
                float2 bv = *(const float2*)&Vt[(j2 * 8 + r) * LDVT + kk * 8 + 2 * c];
                MMA_TF32(o[j2], a0, a1, a2, a3, fu(bv.x), fu(bv.y));
            }
        }
        __syncwarp();  // P reads done before next iter's P stores
    }

    // epilogue: normalize + write [B,S,H*D]
#pragma unroll
    for (int ro = 0; ro < 2; ro++) {
        float inv = 1.0f / ls[ro];
        int row = m0 + w * 16 + r + ro * 8;
#pragma unroll
        for (int j2 = 0; j2 < 8; j2++) {
            int col = j2 * 8 + 2 * c;
            float2 v;
            v.x = o[j2][ro * 2] * inv;
            v.y = o[j2][ro * 2 + 1] * inv;
            *(float2*)&g_att[((size_t)(b * SQ + row)) * HID + h * HD + col] = v;
        }
    }
}

// ---------------------------------------------------------------- launch
extern "C" void kernel_launch(void* const* d_in, const int* in_sizes, int n_in,
                              void* d_out, int out_size) {
    const float* x     = (const float*)d_in[0];
    const float* Wq    = (const float*)d_in[1];
    const float* Wk    = (const float*)d_in[2];
    const float* Wv    = (const float*)d_in[3];
    const float* Wo    = (const float*)d_in[4];
    const float* phase = (const float*)d_in[5];
    const float* amp   = (const float*)d_in[6];
    float* out = (float*)d_out;

    cudaFuncSetAttribute(qkv_gemm, cudaFuncAttributeMaxDynamicSharedMemorySize, GEMM_SMEM);
    cudaFuncSetAttribute(out_gemm, cudaFuncAttributeMaxDynamicSharedMemorySize, GEMM_SMEM);
    cudaFuncSetAttribute(attn_kernel, cudaFuncAttributeMaxDynamicSharedMemorySize, ATT_SMEM);

    prep_kernel<<<8, 256>>>(phase, amp);
    qkv_gemm<<<dim3(8, 32, 3), 256, GEMM_SMEM>>>(x, Wq, Wk, Wv);
    roll_kernel<<<(BH * SQ * (HD / 4)) / 256, 256>>>();
    attn_kernel<<<dim3(16, 16, 2), 256, ATT_SMEM>>>();
    out_gemm<<<dim3(8, 32), 256, GEMM_SMEM>>>(Wo, out);
}